// round 2
// baseline (speedup 1.0000x reference)
#include <cuda_runtime.h>
#include <cstdint>

#define NGROUP 80
#define BEX 8
#define NPG 1024
#define MCENT 512
#define MAXIT 300
#define TOLF 1e-3f

// ---------------- device globals (no allocation allowed) ----------------
__device__ int g_starts[NGROUP];
__device__ int g_flags[MAXIT + 1];
__device__ unsigned int g_bar_count;   // zero-initialized, returns to 0 after each barrier
__device__ unsigned int g_bar_gen;     // monotonically increasing across replays (safe)

// ---------------- threefry2x32 (exact JAX PRNG) ----------------
__device__ __forceinline__ uint32_t rotl32(uint32_t x, int d) { return (x << d) | (x >> (32 - d)); }

__device__ void tf2x32(uint32_t k0, uint32_t k1, uint32_t x0, uint32_t x1,
                       uint32_t& o0, uint32_t& o1) {
    uint32_t ks0 = k0, ks1 = k1, ks2 = k0 ^ k1 ^ 0x1BD11BDAu;
#define RND(r) { x0 += x1; x1 = rotl32(x1, r); x1 ^= x0; }
    x0 += ks0; x1 += ks1;
    RND(13) RND(15) RND(26) RND(6)   x0 += ks1; x1 += ks2 + 1u;
    RND(17) RND(29) RND(16) RND(24)  x0 += ks2; x1 += ks0 + 2u;
    RND(13) RND(15) RND(26) RND(6)   x0 += ks0; x1 += ks1 + 3u;
    RND(17) RND(29) RND(16) RND(24)  x0 += ks1; x1 += ks2 + 4u;
    RND(13) RND(15) RND(26) RND(6)   x0 += ks2; x1 += ks0 + 5u;
#undef RND
    o0 = x0; o1 = x1;
}

// starts = jax.random.randint(jax.random.key(1), (80,), 0, 1024)
// Modern JAX: jax_threefry_partitionable=True (default since 0.4.36):
//   split(key)[1]  ->  k2 = threefry2x32((0,1), counter=(0,1))   [both output words]
//   random_bits(k2, 32, (80,)): element i uses 64-bit counter (hi,lo)=(0,i);
//     32-bit output = o0 ^ o1  (XOR fold of the two threefry output words)
//   span=1024 -> multiplier (2^16 % 1024)^2 % 1024 = 0 -> starts = bits % 1024
__global__ void starts_kernel() {
    int i = threadIdx.x;
    if (i >= NGROUP) return;
    uint32_t c0, c1;
    tf2x32(0u, 1u, 0u, 1u, c0, c1);          // k2 = split(key(1))[1] (partitionable)
    uint32_t o0, o1;
    tf2x32(c0, c1, 0u, (uint32_t)i, o0, o1); // 64-bit counter (0, i)
    g_starts[i] = (int)((o0 ^ o1) & 1023u);
}

// ---------------- grid barrier (80 blocks, all co-resident) ----------------
__device__ void grid_barrier() {
    __syncthreads();
    if (threadIdx.x == 0) {
        volatile unsigned int* vgen = &g_bar_gen;
        unsigned int gen = *vgen;
        __threadfence();
        unsigned int ticket = atomicAdd(&g_bar_count, 1u);
        if (ticket == NGROUP - 1) {
            g_bar_count = 0u;
            __threadfence();
            atomicAdd(&g_bar_gen, 1u);
        } else {
            while (*vgen == gen) { __nanosleep(64); }
        }
        __threadfence();
    }
    __syncthreads();
}

__device__ __forceinline__ float sq3(float a, float b, float c) {
    // ((a*a + b*b) + c*c), non-fused to match XLA's elementwise lowering
    return __fadd_rn(__fadd_rn(__fmul_rn(a, a), __fmul_rn(b, b)), __fmul_rn(c, c));
}

// ---------------- main persistent kernel: FPS + k-means + score ----------------
__global__ void __launch_bounds__(1024, 1)
kmeans_kernel(const float* __restrict__ pos, float* __restrict__ out, int out_size) {
    __shared__ float4 sP[NPG];     // points (w unused)
    __shared__ float4 sC[MCENT];   // centroids (w = |c|^2)
    __shared__ float4 sN[MCENT];   // new centroids
    __shared__ int    sCls[NPG];
    __shared__ float  redV[32];
    __shared__ int    redI[32];
    __shared__ int    sSel;
    __shared__ float  sScore;

    const int g = blockIdx.x;
    const int t = threadIdx.x;
    const int b = g & (BEX - 1);           // group g = r*B + b  ->  example b
    const float* pb = pos + (size_t)b * NPG * 3;

    const float px = pb[t * 3 + 0], py = pb[t * 3 + 1], pz = pb[t * 3 + 2];
    sP[t] = make_float4(px, py, pz, 0.f);
    const float p2 = sq3(px, py, pz);
    __syncthreads();

    const int wid = t >> 5, lane = t & 31;

    // ================= FPS init =================
    int last = g_starts[g];
    float mind = __int_as_float(0x7f800000);   // +inf
    for (int k = 0; k < MCENT; ++k) {
        float4 q = sP[last];                   // uniform broadcast
        if (t == 0) sC[k] = make_float4(q.x, q.y, q.z, sq3(q.x, q.y, q.z));
        float dx = __fsub_rn(px, q.x), dy = __fsub_rn(py, q.y), dz = __fsub_rn(pz, q.z);
        float d = sq3(dx, dy, dz);
        mind = fminf(mind, d);
        // argmax(mind) with FIRST-index tie-break (jnp.argmax)
        float v = mind; int bi = t;
        #pragma unroll
        for (int off = 16; off > 0; off >>= 1) {
            float ov = __shfl_down_sync(0xffffffffu, v, off);
            int   oi = __shfl_down_sync(0xffffffffu, bi, off);
            if (ov > v || (ov == v && oi < bi)) { v = ov; bi = oi; }
        }
        if (lane == 0) { redV[wid] = v; redI[wid] = bi; }
        __syncthreads();
        if (wid == 0) {
            v = redV[lane]; bi = redI[lane];
            #pragma unroll
            for (int off = 16; off > 0; off >>= 1) {
                float ov = __shfl_down_sync(0xffffffffu, v, off);
                int   oi = __shfl_down_sync(0xffffffffu, bi, off);
                if (ov > v || (ov == v && oi < bi)) { v = ov; bi = oi; }
            }
            if (lane == 0) sSel = bi;
        }
        __syncthreads();
        last = sSel;
    }

    // ================= k-means loop (global lockstep) =================
    int bestj = 0;
    for (int iter = 0; iter < MAXIT; ++iter) {
        // ---- assign: d2 = (p2 - 2*dot) + c2, strict '<' keeps first index ----
        float best = __int_as_float(0x7f800000);
        bestj = 0;
        #pragma unroll 8
        for (int j = 0; j < MCENT; ++j) {
            float4 c = sC[j];
            float e = __fadd_rn(__fadd_rn(__fmul_rn(px, c.x), __fmul_rn(py, c.y)),
                                __fmul_rn(pz, c.z));
            float d2 = __fadd_rn(__fsub_rn(p2, __fmul_rn(2.0f, e)), c.w);
            if (d2 < best) { best = d2; bestj = j; }
        }
        sCls[t] = bestj;
        __syncthreads();

        // ---- update: index-ordered per-cluster accumulation (matches scatter-add) ----
        int moved = 0;
        if (t < MCENT) {
            float sx = 0.f, sy = 0.f, sz = 0.f, cnt = 0.f;
            for (int i = 0; i < NPG; ++i) {
                if (sCls[i] == t) {
                    float4 p = sP[i];
                    sx = __fadd_rn(sx, p.x);
                    sy = __fadd_rn(sy, p.y);
                    sz = __fadd_rn(sz, p.z);
                    cnt = __fadd_rn(cnt, 1.0f);
                }
            }
            float4 oc = sC[t];
            float nx, ny, nz;
            if (cnt > 0.f) {
                nx = __fdiv_rn(sx, cnt); ny = __fdiv_rn(sy, cnt); nz = __fdiv_rn(sz, cnt);
            } else {
                nx = oc.x; ny = oc.y; nz = oc.z;
            }
            float dx = __fsub_rn(oc.x, nx), dy = __fsub_rn(oc.y, ny), dz = __fsub_rn(oc.z, nz);
            moved = !(sqrtf(sq3(dx, dy, dz)) < TOLF);
            sN[t] = make_float4(nx, ny, nz, sq3(nx, ny, nz));
        }
        int any = __syncthreads_or(moved);
        if (t == 0 && any) atomicOr(&g_flags[iter], 1);
        grid_barrier();
        int notdone = *((volatile int*)&g_flags[iter]);
        if (t < MCENT) sC[t] = sN[t];
        __syncthreads();
        if (!notdone) break;   // all blocks agree -> same iteration count everywhere
    }

    // ================= score: L1 to assigned (final) centroid =================
    {
        float4 c = sC[bestj];
        float s = fabsf(px - c.x) + fabsf(py - c.y) + fabsf(pz - c.z);
        #pragma unroll
        for (int off = 16; off > 0; off >>= 1)
            s += __shfl_down_sync(0xffffffffu, s, off);
        if (lane == 0) redV[wid] = s;
        __syncthreads();
        if (wid == 0) {
            s = redV[lane];
            #pragma unroll
            for (int off = 16; off > 0; off >>= 1)
                s += __shfl_down_sync(0xffffffffu, s, off);
            if (lane == 0) sScore = s;
        }
        __syncthreads();
    }

    // ================= outputs: [classification f32 | centroids | scores] =================
    int ci = g * NPG + t;                                   // 0 .. 81919
    if (ci < out_size) out[ci] = (float)bestj;
    if (t < MCENT) {
        int base = NGROUP * NPG + g * (MCENT * 3) + t * 3;  // 81920 + ...
        if (base + 2 < out_size) {
            out[base + 0] = sC[t].x;
            out[base + 1] = sC[t].y;
            out[base + 2] = sC[t].z;
        }
    }
    if (t == 0) {
        int si = NGROUP * NPG + NGROUP * MCENT * 3 + g;     // 204800 + g
        if (si < out_size) out[si] = sScore;
    }
}

extern "C" void kernel_launch(void* const* d_in, const int* in_sizes, int n_in,
                              void* d_out, int out_size) {
    const float* pos = (const float*)d_in[0];
    void* flagsAddr = nullptr;
    cudaGetSymbolAddress(&flagsAddr, g_flags);
    cudaMemsetAsync(flagsAddr, 0, sizeof(int) * (MAXIT + 1), 0);
    starts_kernel<<<1, 128>>>();
    kmeans_kernel<<<NGROUP, 1024>>>(pos, (float*)d_out, out_size);
}

// round 3
// speedup vs baseline: 1.9281x; 1.9281x over previous
#include <cuda_runtime.h>
#include <cstdint>

#define NGROUP 80
#define BEX 8
#define NPG 1024
#define MCENT 512
#define MAXIT 300
#define TOLF 1e-3f

// ---------------- device globals (no allocation allowed) ----------------
__device__ int g_starts[NGROUP];
__device__ int g_flags[MAXIT + 1];
__device__ unsigned int g_bar_count;   // returns to 0 after each barrier
__device__ unsigned int g_bar_gen;     // monotonically increasing across replays (safe)

// ---------------- threefry2x32 (exact JAX PRNG, partitionable scheme) ----------------
__device__ __forceinline__ uint32_t rotl32(uint32_t x, int d) { return (x << d) | (x >> (32 - d)); }

__device__ void tf2x32(uint32_t k0, uint32_t k1, uint32_t x0, uint32_t x1,
                       uint32_t& o0, uint32_t& o1) {
    uint32_t ks0 = k0, ks1 = k1, ks2 = k0 ^ k1 ^ 0x1BD11BDAu;
#define RND(r) { x0 += x1; x1 = rotl32(x1, r); x1 ^= x0; }
    x0 += ks0; x1 += ks1;
    RND(13) RND(15) RND(26) RND(6)   x0 += ks1; x1 += ks2 + 1u;
    RND(17) RND(29) RND(16) RND(24)  x0 += ks2; x1 += ks0 + 2u;
    RND(13) RND(15) RND(26) RND(6)   x0 += ks0; x1 += ks1 + 3u;
    RND(17) RND(29) RND(16) RND(24)  x0 += ks1; x1 += ks2 + 4u;
    RND(13) RND(15) RND(26) RND(6)   x0 += ks2; x1 += ks0 + 5u;
#undef RND
    o0 = x0; o1 = x1;
}

__global__ void starts_kernel() {
    int i = threadIdx.x;
    if (i >= NGROUP) return;
    uint32_t c0, c1;
    tf2x32(0u, 1u, 0u, 1u, c0, c1);          // k2 = split(key(1))[1] (partitionable)
    uint32_t o0, o1;
    tf2x32(c0, c1, 0u, (uint32_t)i, o0, o1); // 64-bit counter (0, i)
    g_starts[i] = (int)((o0 ^ o1) & 1023u);
}

// ---------------- grid barrier (80 blocks, all co-resident) ----------------
__device__ void grid_barrier() {
    __syncthreads();
    if (threadIdx.x == 0) {
        volatile unsigned int* vgen = &g_bar_gen;
        unsigned int gen = *vgen;
        __threadfence();
        unsigned int ticket = atomicAdd(&g_bar_count, 1u);
        if (ticket == NGROUP - 1) {
            g_bar_count = 0u;
            __threadfence();
            atomicAdd(&g_bar_gen, 1u);
        } else {
            while (*vgen == gen) { __nanosleep(32); }
        }
        __threadfence();
    }
    __syncthreads();
}

__device__ __forceinline__ float sq3(float a, float b, float c) {
    // ((a*a + b*b) + c*c), non-fused to match XLA's elementwise lowering
    return __fadd_rn(__fadd_rn(__fmul_rn(a, a), __fmul_rn(b, b)), __fmul_rn(c, c));
}

// ---------------- main persistent kernel: FPS + k-means + score ----------------
__global__ void __launch_bounds__(1024, 1)
kmeans_kernel(const float* __restrict__ pos, float* __restrict__ out, int out_size) {
    __shared__ float4   sP[NPG];          // points                             16384 B
    __shared__ float4   sC[MCENT];        // centroids as (-2x,-2y,-2z,|c|^2)    8192 B
    __shared__ uint8_t  whist[32][MCENT]; // per-warp cluster histograms        16384 B
    __shared__ uint16_t sortIdx[NPG];     // cluster-sorted point indices        2048 B
    __shared__ uint16_t sCnt[MCENT];
    __shared__ uint16_t sOff[MCENT];
    __shared__ uint32_t sWsum[16];
    __shared__ uint32_t redV[2][32];
    __shared__ uint32_t redI[2][32];
    __shared__ float    redF[32];
    __shared__ float    sScore;

    const int g = blockIdx.x;
    const int t = threadIdx.x;
    const int b = g & (BEX - 1);           // group g = r*B + b  ->  example b
    const float* pb = pos + (size_t)b * NPG * 3;

    const float px = pb[t * 3 + 0], py = pb[t * 3 + 1], pz = pb[t * 3 + 2];
    sP[t] = make_float4(px, py, pz, 0.f);
    const float p2 = sq3(px, py, pz);
    __syncthreads();

    const int wid = t >> 5, lane = t & 31;

    // ================= FPS init (exact-as-reference distances) =================
    int last = g_starts[g];
    float mind = __int_as_float(0x7f800000);   // +inf
    for (int k = 0; k < MCENT; ++k) {
        float4 q = sP[last];                   // uniform broadcast
        if (t == 0)
            sC[k] = make_float4(__fmul_rn(-2.0f, q.x), __fmul_rn(-2.0f, q.y),
                                __fmul_rn(-2.0f, q.z), sq3(q.x, q.y, q.z));
        float dx = __fsub_rn(px, q.x), dy = __fsub_rn(py, q.y), dz = __fsub_rn(pz, q.z);
        mind = fminf(mind, sq3(dx, dy, dz));
        // argmax(mind), FIRST-index tie-break; positive-float bits are monotonic
        uint32_t bits = __float_as_uint(mind);
        uint32_t wm = __reduce_max_sync(0xffffffffu, bits);
        uint32_t mk = __ballot_sync(0xffffffffu, bits == wm);
        int src = __ffs(mk) - 1;               // lowest lane = first index in warp
        int par = k & 1;
        if (lane == 0) { redV[par][wid] = wm; redI[par][wid] = (uint32_t)((wid << 5) | src); }
        __syncthreads();
        uint32_t v = redV[par][lane];
        uint32_t gm = __reduce_max_sync(0xffffffffu, v);
        uint32_t mk2 = __ballot_sync(0xffffffffu, v == gm);
        int wsel = __ffs(mk2) - 1;             // lowest warp = first index globally
        last = (int)redI[par][wsel];           // next iter writes the other parity slot
    }

    // ================= k-means loop (global lockstep) =================
    int bestj = 0;
    for (int iter = 0; iter < MAXIT; ++iter) {
        // ---- assign: d2 = (p2 + px*(-2cx) + py*(-2cy) + pz*(-2cz)) + c2 ----
        float best = __int_as_float(0x7f800000);
        bestj = 0;
        #pragma unroll 8
        for (int j = 0; j < MCENT; ++j) {
            float4 c = sC[j];
            float acc = __fmaf_rn(pz, c.z, __fmaf_rn(py, c.y, __fmaf_rn(px, c.x, p2)));
            float d2 = __fadd_rn(acc, c.w);
            if (d2 < best) { best = d2; bestj = j; }   // strict '<' keeps first index
        }

        // ---- deterministic stable counting sort of points by cluster ----
        ((uint4*)whist)[t] = make_uint4(0u, 0u, 0u, 0u);   // zero 16KB
        __syncthreads();

        // per-warp stable ranks + per-warp histogram
        uint32_t mm = __match_any_sync(0xffffffffu, (uint32_t)bestj);
        int riw = __popc(mm & ((1u << lane) - 1u));        // rank within warp, lane order
        if (riw == 0) whist[wid][bestj] = (uint8_t)__popc(mm);
        __syncthreads();

        // per-cluster exclusive prefix over warps (in place) + counts
        uint32_t myCnt = 0;
        if (t < MCENT) {
            uint32_t run = 0;
            #pragma unroll
            for (int w = 0; w < 32; ++w) {
                uint32_t v = whist[w][t];
                whist[w][t] = (uint8_t)run;
                run += v;
            }
            myCnt = run;
            sCnt[t] = (uint16_t)run;
        }
        // block-wide exclusive prefix sum over the 512 counts (16 active warps)
        uint32_t exclInWarp = 0;
        if (t < MCENT) {
            uint32_t x = myCnt;
            #pragma unroll
            for (int o = 1; o < 32; o <<= 1) {
                uint32_t y = __shfl_up_sync(0xffffffffu, x, o);
                if (lane >= o) x += y;
            }
            exclInWarp = x - myCnt;
            if (lane == 31) sWsum[wid] = x;                // inclusive warp total
        }
        __syncthreads();
        if (wid == 0) {
            uint32_t wv = (lane < 16) ? sWsum[lane] : 0u;  // exclusive scan of 16 totals
            uint32_t x = wv;
            #pragma unroll
            for (int o = 1; o < 16; o <<= 1) {
                uint32_t y = __shfl_up_sync(0xffffffffu, x, o);
                if (lane >= o) x += y;
            }
            if (lane < 16) sWsum[lane] = x - wv;
        }
        __syncthreads();
        if (t < MCENT) sOff[t] = (uint16_t)(sWsum[wid] + exclInWarp);
        __syncthreads();

        // scatter point indices; ascending-index order preserved per cluster
        {
            uint32_t pw = whist[wid][bestj];
            uint32_t rank = (uint32_t)sOff[bestj] + pw + (uint32_t)riw;
            sortIdx[rank] = (uint16_t)t;
        }
        __syncthreads();

        // per-cluster ordered fold + centroid update + convergence
        int moved = 0;
        if (t < MCENT) {
            uint32_t n = sCnt[t], base = sOff[t];
            float sx = 0.f, sy = 0.f, sz = 0.f;
            for (uint32_t k2 = 0; k2 < n; ++k2) {
                float4 p = sP[sortIdx[base + k2]];
                sx = __fadd_rn(sx, p.x);
                sy = __fadd_rn(sy, p.y);
                sz = __fadd_rn(sz, p.z);
            }
            float4 cs = sC[t];
            float ocx = __fmul_rn(-0.5f, cs.x);   // exact recovery of coords
            float ocy = __fmul_rn(-0.5f, cs.y);
            float ocz = __fmul_rn(-0.5f, cs.z);
            float cntf = (float)n;
            float nx, ny, nz;
            if (n > 0) {
                nx = __fdiv_rn(sx, cntf); ny = __fdiv_rn(sy, cntf); nz = __fdiv_rn(sz, cntf);
            } else {
                nx = ocx; ny = ocy; nz = ocz;
            }
            float dx = __fsub_rn(ocx, nx), dy = __fsub_rn(ocy, ny), dz = __fsub_rn(ocz, nz);
            moved = !(sqrtf(sq3(dx, dy, dz)) < TOLF);
            sC[t] = make_float4(__fmul_rn(-2.0f, nx), __fmul_rn(-2.0f, ny),
                                __fmul_rn(-2.0f, nz), sq3(nx, ny, nz));
        }
        int any = __syncthreads_or(moved);
        if (t == 0 && any) atomicOr(&g_flags[iter], 1);
        grid_barrier();
        int notdone = *((volatile int*)&g_flags[iter]);
        if (!notdone) break;   // all blocks agree -> same iteration count everywhere
    }

    // ================= score: L1 to assigned (final) centroid =================
    {
        float4 cs = sC[bestj];
        float cx = __fmul_rn(-0.5f, cs.x), cy = __fmul_rn(-0.5f, cs.y), cz = __fmul_rn(-0.5f, cs.z);
        float s = fabsf(px - cx) + fabsf(py - cy) + fabsf(pz - cz);
        #pragma unroll
        for (int off = 16; off > 0; off >>= 1)
            s += __shfl_down_sync(0xffffffffu, s, off);
        if (lane == 0) redF[wid] = s;
        __syncthreads();
        if (wid == 0) {
            s = redF[lane];
            #pragma unroll
            for (int off = 16; off > 0; off >>= 1)
                s += __shfl_down_sync(0xffffffffu, s, off);
            if (lane == 0) sScore = s;
        }
        __syncthreads();
    }

    // ================= outputs: [classification | centroids | scores] =================
    int ci = g * NPG + t;                                   // 0 .. 81919
    if (ci < out_size) out[ci] = (float)bestj;
    if (t < MCENT) {
        int base = NGROUP * NPG + g * (MCENT * 3) + t * 3;  // 81920 + ...
        if (base + 2 < out_size) {
            float4 cs = sC[t];
            out[base + 0] = __fmul_rn(-0.5f, cs.x);
            out[base + 1] = __fmul_rn(-0.5f, cs.y);
            out[base + 2] = __fmul_rn(-0.5f, cs.z);
        }
    }
    if (t == 0) {
        int si = NGROUP * NPG + NGROUP * MCENT * 3 + g;     // 204800 + g
        if (si < out_size) out[si] = sScore;
    }
}

extern "C" void kernel_launch(void* const* d_in, const int* in_sizes, int n_in,
                              void* d_out, int out_size) {
    const float* pos = (const float*)d_in[0];
    void* flagsAddr = nullptr;
    cudaGetSymbolAddress(&flagsAddr, g_flags);
    cudaMemsetAsync(flagsAddr, 0, sizeof(int) * (MAXIT + 1), 0);
    starts_kernel<<<1, 128>>>();
    kmeans_kernel<<<NGROUP, 1024>>>(pos, (float*)d_out, out_size);
}

// round 4
// speedup vs baseline: 2.4591x; 1.2754x over previous
#include <cuda_runtime.h>
#include <cstdint>

#define NGROUP 80
#define BEX 8
#define NPG 1024
#define MCENT 512
#define NTHR 512
#define MAXIT 300
#define TOLF 1e-3f

// ---------------- device globals (no allocation allowed) ----------------
__device__ int g_starts[NGROUP];
__device__ int g_flags[MAXIT + 1];
__device__ unsigned int g_bar_count;   // returns to 0 after each barrier
__device__ unsigned int g_bar_gen;     // monotonically increasing across replays (safe)

// ---------------- threefry2x32 (exact JAX PRNG, partitionable scheme) ----------------
__device__ __forceinline__ uint32_t rotl32(uint32_t x, int d) { return (x << d) | (x >> (32 - d)); }

__device__ void tf2x32(uint32_t k0, uint32_t k1, uint32_t x0, uint32_t x1,
                       uint32_t& o0, uint32_t& o1) {
    uint32_t ks0 = k0, ks1 = k1, ks2 = k0 ^ k1 ^ 0x1BD11BDAu;
#define RND(r) { x0 += x1; x1 = rotl32(x1, r); x1 ^= x0; }
    x0 += ks0; x1 += ks1;
    RND(13) RND(15) RND(26) RND(6)   x0 += ks1; x1 += ks2 + 1u;
    RND(17) RND(29) RND(16) RND(24)  x0 += ks2; x1 += ks0 + 2u;
    RND(13) RND(15) RND(26) RND(6)   x0 += ks0; x1 += ks1 + 3u;
    RND(17) RND(29) RND(16) RND(24)  x0 += ks1; x1 += ks2 + 4u;
    RND(13) RND(15) RND(26) RND(6)   x0 += ks2; x1 += ks0 + 5u;
#undef RND
    o0 = x0; o1 = x1;
}

__global__ void starts_kernel() {
    int i = threadIdx.x;
    if (i >= NGROUP) return;
    uint32_t c0, c1;
    tf2x32(0u, 1u, 0u, 1u, c0, c1);          // k2 = split(key(1))[1] (partitionable)
    uint32_t o0, o1;
    tf2x32(c0, c1, 0u, (uint32_t)i, o0, o1); // 64-bit counter (0, i)
    g_starts[i] = (int)((o0 ^ o1) & 1023u);
}

// ---------------- grid barrier (80 blocks, all co-resident) ----------------
__device__ void grid_barrier() {
    __syncthreads();
    if (threadIdx.x == 0) {
        volatile unsigned int* vgen = &g_bar_gen;
        unsigned int gen = *vgen;
        __threadfence();
        unsigned int ticket = atomicAdd(&g_bar_count, 1u);
        if (ticket == NGROUP - 1) {
            g_bar_count = 0u;
            __threadfence();
            atomicAdd(&g_bar_gen, 1u);
        } else {
            while (*vgen == gen) { __nanosleep(32); }
        }
        __threadfence();
    }
    __syncthreads();
}

__device__ __forceinline__ float sq3(float a, float b, float c) {
    // ((a*a + b*b) + c*c), non-fused (matches reference-critical FPS/update math)
    return __fadd_rn(__fadd_rn(__fmul_rn(a, a), __fmul_rn(b, b)), __fmul_rn(c, c));
}

// ---------------- main persistent kernel: FPS + k-means + score ----------------
__global__ void __launch_bounds__(NTHR, 1)
kmeans_kernel(const float* __restrict__ pos, float* __restrict__ out, int out_size) {
    __shared__ float4   sP[NPG];          // points                             16384 B
    __shared__ float4   sC[MCENT];        // centroids as (-2x,-2y,-2z,|c|^2)    8192 B
    __shared__ uint8_t  whist[32][MCENT]; // rows 0-15: A-points, 16-31: B      16384 B
    __shared__ uint16_t sortIdx[NPG];     // cluster-sorted point indices        2048 B
    __shared__ uint16_t sCnt[MCENT];
    __shared__ uint16_t sOff[MCENT];
    __shared__ uint32_t sWsum[16];
    __shared__ uint32_t redV[2][16];
    __shared__ uint32_t redI[2][16];
    __shared__ float    redF[16];
    __shared__ float    sScore;

    const int g = blockIdx.x;
    const int t = threadIdx.x;
    const int b = g & (BEX - 1);           // group g = r*B + b  ->  example b
    const float* pb = pos + (size_t)b * NPG * 3;

    // two points per thread: A = t, B = t + 512
    const float pxA = pb[t * 3 + 0], pyA = pb[t * 3 + 1], pzA = pb[t * 3 + 2];
    const float pxB = pb[(t + NTHR) * 3 + 0], pyB = pb[(t + NTHR) * 3 + 1], pzB = pb[(t + NTHR) * 3 + 2];
    sP[t]        = make_float4(pxA, pyA, pzA, 0.f);
    sP[t + NTHR] = make_float4(pxB, pyB, pzB, 0.f);
    __syncthreads();

    const int wid = t >> 5, lane = t & 31;

    // ================= FPS init (exact-as-reference distances) =================
    int last = g_starts[g];
    float mindA = __int_as_float(0x7f800000);
    float mindB = __int_as_float(0x7f800000);
    for (int k = 0; k < MCENT; ++k) {
        float4 q = sP[last];                   // uniform broadcast
        if (t == 0)
            sC[k] = make_float4(__fmul_rn(-2.0f, q.x), __fmul_rn(-2.0f, q.y),
                                __fmul_rn(-2.0f, q.z), sq3(q.x, q.y, q.z));
        {
            float dx = __fsub_rn(pxA, q.x), dy = __fsub_rn(pyA, q.y), dz = __fsub_rn(pzA, q.z);
            mindA = fminf(mindA, sq3(dx, dy, dz));
        }
        {
            float dx = __fsub_rn(pxB, q.x), dy = __fsub_rn(pyB, q.y), dz = __fsub_rn(pzB, q.z);
            mindB = fminf(mindB, sq3(dx, dy, dz));
        }
        // argmax(mind), FIRST-index tie-break: value-max + min-index-among-max.
        uint32_t bA = __float_as_uint(mindA);  // positive-float bits monotonic
        uint32_t bB = __float_as_uint(mindB);
        uint32_t val = (bB > bA) ? bB : bA;
        uint32_t idx = (bB > bA) ? (uint32_t)(t + NTHR) : (uint32_t)t;  // tie -> A (smaller idx)
        uint32_t wm  = __reduce_max_sync(0xffffffffu, val);
        uint32_t cnd = (val == wm) ? idx : 0xFFFFu;
        uint32_t wix = __reduce_min_sync(0xffffffffu, cnd);
        int par = k & 1;
        if (lane == 0) { redV[par][wid] = wm; redI[par][wid] = wix; }
        __syncthreads();
        uint32_t v  = (lane < 16) ? redV[par][lane] : 0u;
        uint32_t gm = __reduce_max_sync(0xffffffffu, v);
        uint32_t c2 = (lane < 16 && v == gm) ? redI[par][lane] : 0xFFFFu;
        last = (int)__reduce_min_sync(0xffffffffu, c2);   // smallest global index
    }

    // ================= k-means loop (global lockstep) =================
    int bjA = 0, bjB = 0;
    for (int iter = 0; iter < MAXIT; ++iter) {
        // ---- assign: argmin_j (c2 + px*(-2cx) + py*(-2cy) + pz*(-2cz)) ----
        float bestA = __int_as_float(0x7f800000);
        float bestB = __int_as_float(0x7f800000);
        bjA = 0; bjB = 0;
        #pragma unroll 8
        for (int j = 0; j < MCENT; ++j) {
            float4 c = sC[j];
            float aA = __fmaf_rn(pzA, c.z, __fmaf_rn(pyA, c.y, __fmaf_rn(pxA, c.x, c.w)));
            float aB = __fmaf_rn(pzB, c.z, __fmaf_rn(pyB, c.y, __fmaf_rn(pxB, c.x, c.w)));
            if (aA < bestA) { bestA = aA; bjA = j; }   // strict '<' keeps first index
            if (aB < bestB) { bestB = aB; bjB = j; }
        }

        // ---- deterministic stable counting sort of points by cluster ----
        ((uint4*)whist)[t * 2]     = make_uint4(0u, 0u, 0u, 0u);   // zero 16KB
        ((uint4*)whist)[t * 2 + 1] = make_uint4(0u, 0u, 0u, 0u);
        __syncthreads();

        // per-warp stable ranks + per-warp histograms (A rows 0-15, B rows 16-31)
        uint32_t below = (1u << lane) - 1u;
        uint32_t mmA = __match_any_sync(0xffffffffu, (uint32_t)bjA);
        int riwA = __popc(mmA & below);
        if (riwA == 0) whist[wid][bjA] = (uint8_t)__popc(mmA);
        uint32_t mmB = __match_any_sync(0xffffffffu, (uint32_t)bjB);
        int riwB = __popc(mmB & below);
        if (riwB == 0) whist[16 + wid][bjB] = (uint8_t)__popc(mmB);
        __syncthreads();

        // per-cluster exclusive prefix over the 32 rows (in place) + counts
        uint32_t run = 0;
        #pragma unroll
        for (int w = 0; w < 32; ++w) {
            uint32_t v = whist[w][t];
            whist[w][t] = (uint8_t)run;
            run += v;
        }
        sCnt[t] = (uint16_t)run;

        // block-wide exclusive prefix sum over the 512 counts (16 warps)
        uint32_t x = run;
        #pragma unroll
        for (int o = 1; o < 32; o <<= 1) {
            uint32_t y = __shfl_up_sync(0xffffffffu, x, o);
            if (lane >= o) x += y;
        }
        uint32_t exclInWarp = x - run;
        if (lane == 31) sWsum[wid] = x;
        __syncthreads();
        if (wid == 0) {
            uint32_t wv = (lane < 16) ? sWsum[lane] : 0u;
            uint32_t xx = wv;
            #pragma unroll
            for (int o = 1; o < 16; o <<= 1) {
                uint32_t y = __shfl_up_sync(0xffffffffu, xx, o);
                if (lane >= o) xx += y;
            }
            if (lane < 16) sWsum[lane] = xx - wv;
        }
        __syncthreads();
        sOff[t] = (uint16_t)(sWsum[wid] + exclInWarp);
        __syncthreads();

        // scatter point indices; ascending-index order preserved per cluster
        {
            uint32_t rkA = (uint32_t)sOff[bjA] + whist[wid][bjA] + (uint32_t)riwA;
            sortIdx[rkA] = (uint16_t)t;
            uint32_t rkB = (uint32_t)sOff[bjB] + whist[16 + wid][bjB] + (uint32_t)riwB;
            sortIdx[rkB] = (uint16_t)(t + NTHR);
        }
        __syncthreads();

        // per-cluster ordered fold + centroid update + convergence
        int moved = 0;
        {
            uint32_t n = sCnt[t], base = sOff[t];
            float sx = 0.f, sy = 0.f, sz = 0.f;
            for (uint32_t k2 = 0; k2 < n; ++k2) {
                float4 p = sP[sortIdx[base + k2]];
                sx = __fadd_rn(sx, p.x);
                sy = __fadd_rn(sy, p.y);
                sz = __fadd_rn(sz, p.z);
            }
            float4 cs = sC[t];
            float ocx = __fmul_rn(-0.5f, cs.x);   // exact recovery of coords
            float ocy = __fmul_rn(-0.5f, cs.y);
            float ocz = __fmul_rn(-0.5f, cs.z);
            float cntf = (float)n;
            float nx, ny, nz;
            if (n > 0) {
                nx = __fdiv_rn(sx, cntf); ny = __fdiv_rn(sy, cntf); nz = __fdiv_rn(sz, cntf);
            } else {
                nx = ocx; ny = ocy; nz = ocz;
            }
            float dx = __fsub_rn(ocx, nx), dy = __fsub_rn(ocy, ny), dz = __fsub_rn(ocz, nz);
            moved = !(sqrtf(sq3(dx, dy, dz)) < TOLF);
            sC[t] = make_float4(__fmul_rn(-2.0f, nx), __fmul_rn(-2.0f, ny),
                                __fmul_rn(-2.0f, nz), sq3(nx, ny, nz));
        }
        int any = __syncthreads_or(moved);
        if (t == 0 && any) atomicOr(&g_flags[iter], 1);
        grid_barrier();
        int notdone = *((volatile int*)&g_flags[iter]);
        if (!notdone) break;   // all blocks agree -> same iteration count everywhere
    }

    // ================= score: L1 to assigned (final) centroids =================
    {
        float4 ca = sC[bjA];
        float cax = __fmul_rn(-0.5f, ca.x), cay = __fmul_rn(-0.5f, ca.y), caz = __fmul_rn(-0.5f, ca.z);
        float4 cb = sC[bjB];
        float cbx = __fmul_rn(-0.5f, cb.x), cby = __fmul_rn(-0.5f, cb.y), cbz = __fmul_rn(-0.5f, cb.z);
        float s = fabsf(pxA - cax) + fabsf(pyA - cay) + fabsf(pzA - caz)
                + fabsf(pxB - cbx) + fabsf(pyB - cby) + fabsf(pzB - cbz);
        #pragma unroll
        for (int off = 16; off > 0; off >>= 1)
            s += __shfl_down_sync(0xffffffffu, s, off);
        if (lane == 0) redF[wid] = s;
        __syncthreads();
        if (wid == 0) {
            float v = (lane < 16) ? redF[lane] : 0.f;
            #pragma unroll
            for (int off = 8; off > 0; off >>= 1)
                v += __shfl_down_sync(0xffffffffu, v, off);
            if (lane == 0) sScore = v;
        }
        __syncthreads();
    }

    // ================= outputs: [classification | centroids | scores] =================
    int ci = g * NPG + t;
    if (ci < out_size) out[ci] = (float)bjA;
    int ci2 = g * NPG + NTHR + t;
    if (ci2 < out_size) out[ci2] = (float)bjB;
    {
        int base = NGROUP * NPG + g * (MCENT * 3) + t * 3;
        if (base + 2 < out_size) {
            float4 cs = sC[t];
            out[base + 0] = __fmul_rn(-0.5f, cs.x);
            out[base + 1] = __fmul_rn(-0.5f, cs.y);
            out[base + 2] = __fmul_rn(-0.5f, cs.z);
        }
    }
    if (t == 0) {
        int si = NGROUP * NPG + NGROUP * MCENT * 3 + g;
        if (si < out_size) out[si] = sScore;
    }
}

extern "C" void kernel_launch(void* const* d_in, const int* in_sizes, int n_in,
                              void* d_out, int out_size) {
    const float* pos = (const float*)d_in[0];
    void* flagsAddr = nullptr;
    cudaGetSymbolAddress(&flagsAddr, g_flags);
    cudaMemsetAsync(flagsAddr, 0, sizeof(int) * (MAXIT + 1), 0);
    starts_kernel<<<1, 128>>>();
    kmeans_kernel<<<NGROUP, NTHR>>>(pos, (float*)d_out, out_size);
}